// round 16
// baseline (speedup 1.0000x reference)
#include <cuda_runtime.h>
#include <cuda_bf16.h>

// Problem constants (fixed shapes from reference setup_inputs)
#define BB 4
#define NN 16384
#define PP 1024
#define CC 128
#define NS 64
#define R2 0.04f

#define NQBLK (BB * PP / 4)   // 1024 query blocks (FIRST - R6 proven ordering)
#define NTBLK (BB * 512 * 4)  // 8192 transpose blocks (behind)

// Scratch (allocations forbidden; __device__ globals)
__device__ float g_ftrans[(size_t)BB * NN * CC];   // (B, N, C), 32 MB
__device__ int   g_idx[BB * PP * NS];              // masked gather indices

// Swizzled tile address: 64 s-rows x 64 channels, 16B-group XOR swizzle.
__device__ __forceinline__ int taddr(int s, int ch) {
    return s * 64 + (((ch >> 2) ^ (s & 15)) << 2) + (ch & 3);
}

// ---------------------------------------------------------------------------
// Kernel 1 (union grid, R6 ordering): blocks [0, NQBLK) = ball query
// (4 centers/block; 1024-pt iterations = 4 point-groups of 256; 16 ballots in
// two independent pipelined chains; ONE barrier per iteration; per-lane state
// packed so masks don't live across the barrier; groups processed in index
// order after the barrier -> exact ordered compaction).
// Blocks [NQBLK, NQBLK+NTBLK) = feature transpose (B,C,N) -> (B,N,C).
// ---------------------------------------------------------------------------
__global__ void __launch_bounds__(256) prep_kernel(
    const float* __restrict__ f, const float* __restrict__ xyz,
    const float* __restrict__ new_xyz, float* __restrict__ out) {
    const int bi = blockIdx.x;
    const int t = threadIdx.x;
    if (bi < NQBLK) {
        // -------- ball query: 4 centers per block, shared scan --------
        __shared__ int sidx[4][NS];
        __shared__ unsigned long long wc[2][4][8];  // [buf][group][warp]
        const int warp = t >> 5;
        const int lane = t & 31;
        const int pb0 = bi * 4;              // first center id (same batch)
        const int b = pb0 >> 10;
        const float* xb = xyz + (size_t)b * NN * 3;

        float qx[4], qy[4], qz[4];
#pragma unroll
        for (int g = 0; g < 4; g++) {
            qx[g] = new_xyz[(size_t)(pb0 + g) * 3 + 0];
            qy[g] = new_xyz[(size_t)(pb0 + g) * 3 + 1];
            qz[g] = new_xyz[(size_t)(pb0 + g) * 3 + 2];
        }

        // prefetch iteration 0: thread owns points base + u*256 + t, u=0..3
        float px[4], py[4], pz[4];
#pragma unroll
        for (int u = 0; u < 4; u++) {
            px[u] = xb[(u * 256 + t) * 3 + 0];
            py[u] = xb[(u * 256 + t) * 3 + 1];
            pz[u] = xb[(u * 256 + t) * 3 + 2];
        }

        int cnt[4] = {0, 0, 0, 0};
        int sel = 0;
        const unsigned lm = (1u << lane) - 1u;
        for (int base = 0; base < NN; base += 1024) {
            unsigned hbits = 0;      // bit (u*4+g): hit of group u, center g
            unsigned pp[4];          // pp[u]: 4x8-bit popc(m & lanemask)
#pragma unroll
            for (int u = 0; u < 4; u++) {
                unsigned long long c4 = 0;
                unsigned ppu = 0;
#pragma unroll
                for (int g = 0; g < 4; g++) {
                    // JAX f32 rounding: no FMA contraction, L-to-R sum.
                    const float dx = __fadd_rn(qx[g], -px[u]);
                    const float dy = __fadd_rn(qy[g], -py[u]);
                    const float dz = __fadd_rn(qz[g], -pz[u]);
                    const float d2 = __fadd_rn(
                        __fadd_rn(__fmul_rn(dx, dx), __fmul_rn(dy, dy)),
                        __fmul_rn(dz, dz));
                    const bool h = d2 < R2;
                    const unsigned m = __ballot_sync(0xffffffffu, h);
                    hbits |= (unsigned)h << (u * 4 + g);
                    ppu |= (unsigned)__popc(m & lm) << (8 * g);
                    c4 |= (unsigned long long)__popc(m) << (16 * g);
                }
                pp[u] = ppu;
                if (lane == 0) wc[sel][u][warp] = c4;
            }

            // prefetch next 1024 points BEFORE the barrier (coords now dead)
            const int nb = base + 1024;
            if (nb < NN) {
#pragma unroll
                for (int u = 0; u < 4; u++) {
                    px[u] = xb[(nb + u * 256 + t) * 3 + 0];
                    py[u] = xb[(nb + u * 256 + t) * 3 + 1];
                    pz[u] = xb[(nb + u * 256 + t) * 3 + 2];
                }
            }
            __syncthreads();   // the ONLY barrier per 1024-pt iteration

            // groups in index order: exact ordered compaction
#pragma unroll
            for (int u = 0; u < 4; u++) {
                unsigned long long pre = 0, tot = 0;
#pragma unroll
                for (int w = 0; w < 8; w++) {
                    const unsigned long long v = wc[sel][u][w];
                    if (w < warp) pre += v;
                    tot += v;
                }
#pragma unroll
                for (int g = 0; g < 4; g++) {
                    const int p0 = (int)((pre >> (16 * g)) & 0xffff);
                    const int pos = cnt[g] + p0 + (int)((pp[u] >> (8 * g)) & 0xff);
                    if (((hbits >> (u * 4 + g)) & 1u) && pos < NS)
                        sidx[g][pos] = base + u * 256 + t;
                    cnt[g] += (int)((tot >> (16 * g)) & 0xffff);
                }
            }
            sel ^= 1;
            if (cnt[0] >= NS && cnt[1] >= NS && cnt[2] >= NS && cnt[3] >= NS)
                break;
        }
        __syncthreads();       // sidx visible to all warps

        // ---- outputs: thread t handles center g = t>>6, slot s = t&63 ----
        {
            const int g = t >> 6;
            const int s = t & 63;
            const int cn = cnt[g] < NS ? cnt[g] : NS;
            const int first = (cn > 0) ? sidx[g][0] : NN;
            const bool real = (s < cn);
            const int v = real ? sidx[g][s] : NN;
            const size_t o = (size_t)(pb0 + g) * NS;
            g_idx[o + s] = v;   // masked (pad -> NN)
            float* out_idx =
                out + (size_t)BB * 131 * PP * NS + (size_t)BB * 3 * PP * NS;
            out_idx[o + s] = (float)(real ? v : first);   // idx0 (pad -> first)
        }
    } else {
        // ---------------- transpose (B,C,N) -> (B,N,C) ----------------
        __shared__ float tile[32][33];
        const int tb = bi - NQBLK;        // 0..8191
        const int b = tb >> 11;           // 2048 blocks per batch
        const int rem = tb & 2047;
        const int nBase = (rem >> 2) * 32;
        const int cBase = (rem & 3) * 32;
        const float* fb = f + (size_t)b * CC * NN;
        float* ob = g_ftrans + (size_t)b * NN * CC;
        const int tx = t & 31, ty = t >> 5;  // 32 x 8
#pragma unroll
        for (int i = 0; i < 32; i += 8)
            tile[ty + i][tx] = fb[(size_t)(cBase + ty + i) * NN + nBase + tx];
        __syncthreads();
#pragma unroll
        for (int i = 0; i < 32; i += 8)
            ob[(size_t)(nBase + ty + i) * CC + cBase + tx] = tile[tx][ty + i];
    }
}

// ---------------------------------------------------------------------------
// Kernel 2: gather + group (R6 exact version: xyz channels here, where their
// scattered-load latency hides under bandwidth). Block per (chunk, p, b).
// ---------------------------------------------------------------------------
__global__ void __launch_bounds__(256, 8) gather_kernel(
    const float* __restrict__ xyz, const float* __restrict__ new_xyz,
    float* __restrict__ out) {
    __shared__ float ftile[64 * 64];    // 16 KB, swizzled
    __shared__ int smidx[NS];

    const int chunk = blockIdx.x;       // 0 / 1
    const int p = blockIdx.y;
    const int b = blockIdx.z;
    const int t = threadIdx.x;
    const int warp = t >> 5;
    const int lane = t & 31;

    if (t < NS) smidx[t] = g_idx[((size_t)b * PP + p) * NS + t];
    __syncthreads();

    // Phase A: gather. Warp handles 2 s-rows per iter (16 lanes x float4 each).
    const float* fb = g_ftrans + (size_t)b * NN * CC + chunk * 64;
    const int c4 = lane & 15;           // 16B group within the row
#pragma unroll
    for (int i = 0; i < 4; i++) {
        const int row = warp * 8 + i * 2 + (lane >> 4);
        const int n = smidx[row];
        float4 v = make_float4(0.f, 0.f, 0.f, 0.f);
        if (n < NN) v = *(const float4*)&fb[(size_t)n * CC + c4 * 4];
        *(float4*)&ftile[row * 64 + ((c4 ^ (row & 15)) << 2)] = v;
    }
    __syncthreads();

    // Phase B: write 64 channels x 64 s, STG.128 along s.
    float* nfb = out + (((size_t)b * 131 + 3 + chunk * 64) * PP + p) * NS;
    const int ch = t >> 2;              // 0..63 (within chunk)
#pragma unroll
    for (int k = 0; k < 4; k++) {
        const int sg = (t & 3) + 4 * k; // 0..15 (group of 4 s)
        float4 v;
        v.x = ftile[taddr(4 * sg + 0, ch)];
        v.y = ftile[taddr(4 * sg + 1, ch)];
        v.z = ftile[taddr(4 * sg + 2, ch)];
        v.w = ftile[taddr(4 * sg + 3, ch)];
        *(float4*)&nfb[(size_t)ch * PP * NS + sg * 4] = v;
    }

    // xyz channels: grouped_xyz + xyz_feature (chunk 0 only)
    if (chunk == 0 && t < 192) {
        const int s = t & 63;
        const int c = t >> 6;   // 0..2
        const int n = smidx[s];
        const float q = new_xyz[((size_t)b * PP + p) * 3 + c];
        const float src = (n < NN) ? xyz[((size_t)b * NN + n) * 3 + c] : 1000000.0f;
        const float g = __fadd_rn(src, -q);
        float* gx = out + (size_t)BB * 131 * PP * NS;
        gx[(((size_t)b * 3 + c) * PP + p) * NS + s] = g;
        const float xf = (g > 100000.0f) ? 0.0f : g;
        out[(((size_t)b * 131 + c) * PP + p) * NS + s] = xf / 0.2f;
    }
}

// ---------------------------------------------------------------------------
extern "C" void kernel_launch(void* const* d_in, const int* in_sizes, int n_in,
                              void* d_out, int out_size) {
    const float* xyz      = (const float*)d_in[0];  // (B, N, 3)
    const float* new_xyz  = (const float*)d_in[1];  // (B, P, 3)
    const float* features = (const float*)d_in[2];  // (B, C, N)
    float* out = (float*)d_out;

    prep_kernel<<<NQBLK + NTBLK, 256>>>(features, xyz, new_xyz, out);
    gather_kernel<<<dim3(2, PP, BB), 256>>>(xyz, new_xyz, out);
}